// round 9
// baseline (speedup 1.0000x reference)
#include <cuda_runtime.h>

#define W 224
#define H 224
#define BC 192
#define STEPS 32
#define BANDS 5
#define RPB 45               // bands 0-3: 45 full rows; band 4: 43 full + bottom
#define TPB 128
#define NW 4
#define CGRP 2               // column groups: [0,123], [124,223]
#define GRID (BC * CGRP * BANDS)   // 1920 ~= 148 SMs * 13 blocks (single wave)

// g_hist[bc][j] = differential histogram; finalize does the 32-bin cumsum.
__device__ int g_hist[BC * STEPS];
__device__ unsigned int g_count;

// bin = searchsorted(linspace(0,1,32), f, 'left'); bit-exact (validated R6-R8):
// ceil anchor + two exact-grid fixups (FFMA(fr,s,-s) == fl((fr-1)*s), fr integral).
__device__ __forceinline__ int binof(float f) {
    const float step = 1.0f / 31.0f;
    float fr = ceilf(f * 31.0f);                 // integral, in [0, 31]
    int g = (int)fr;
    if (__fmaf_rn(fr, step, -step) >= f) g--;    // t_{fr-1} >= f
    if (fr < 31.0f && fr * step < f)     g++;    // t_fr < f  (t_31 = 1.0)
    return g;
}

__global__ __launch_bounds__(TPB) void ecc_kernel(const float* __restrict__ x,
                                                  float* __restrict__ out) {
    // Per-thread private histogram columns; 128 % 32 == 0 => conflict-free.
    __shared__ int hist[STEPS][TPB];
    __shared__ bool s_last;

    const int tid  = threadIdx.x;
    const int wid  = tid >> 5;
    const int lane = tid & 31;

    const int cg   = blockIdx.x & 1;
    const int tmp  = blockIdx.x >> 1;
    const int band = tmp % BANDS;
    const int bc   = tmp / BANDS;
    const int r0   = band * RPB;

    const int col  = 31 * (4 * cg + wid) + lane;     // overlapped-warp column map
    const bool act  = (lane < 31) && (col <= 223);
    const bool hasR = act && (col < 223);
    const int  inc  = act  ? 1 : 0;                  // loop-invariant addends
    const int  incR = hasR ? 1 : 0;
    const int  colc = (col <= 223) ? col : 223;

#pragma unroll
    for (int j = 0; j < STEPS; j++) hist[j][tid] = 0;
    __syncthreads();

    const float* p = x + (size_t)bc * (H * W) + (size_t)r0 * W + colc;

    int b  = binof(__ldg(p));
    int br = __shfl_down_sync(0xffffffffu, b, 1);    // valid for lanes 0..30

    if (band != BANDS - 1) {
#pragma unroll 5
        for (int it = 0; it < RPB; it++) {           // 45 full rows
            p += W;
            const int nb  = binof(__ldg(p));
            const int nbr = __shfl_down_sync(0xffffffffu, nb, 1);
            const int e1 = max(b, br);
            const int e2 = max(b, nb);
            const int q  = max(e1, max(nb, nbr));
            hist[b][tid]  += inc;                    // vertex
            hist[e2][tid] -= inc;                    // v-edge
            hist[e1][tid] -= incR;                   // h-edge
            hist[q][tid]  += incR;                   // square
            b = nb; br = nbr;
        }
    } else {
#pragma unroll 5
        for (int it = 0; it < RPB - 2; it++) {       // 43 full rows (180..222)
            p += W;
            const int nb  = binof(__ldg(p));
            const int nbr = __shfl_down_sync(0xffffffffu, nb, 1);
            const int e1 = max(b, br);
            const int e2 = max(b, nb);
            const int q  = max(e1, max(nb, nbr));
            hist[b][tid]  += inc;
            hist[e2][tid] -= inc;
            hist[e1][tid] -= incR;
            hist[q][tid]  += incR;
            b = nb; br = nbr;
        }
        // row 223: vertex + h-edge only
        hist[b][tid] += inc;
        hist[max(b, br)][tid] -= incR;
    }
    __syncthreads();

    // Block reduction: warp w owns bins {w, w+4, ..., w+28}.
    for (int j = wid; j < STEPS; j += NW) {
        int sum = 0;
#pragma unroll
        for (int t = lane; t < TPB; t += 32) sum += hist[j][t];
#pragma unroll
        for (int o = 16; o; o >>= 1) sum += __shfl_down_sync(0xffffffffu, sum, o);
        if (lane == 0) atomicAdd(&g_hist[bc * STEPS + j], sum);
    }

    // Last-block-done: cumsum -> out, reset scratch for next graph replay.
    __threadfence();
    __syncthreads();
    if (tid == 0)
        s_last = (atomicAdd(&g_count, 1u) == (unsigned)(GRID - 1));
    __syncthreads();

    if (s_last) {
        __threadfence();
        for (int g2 = wid; g2 < BC; g2 += NW) {
            int v = __ldcg(&g_hist[g2 * STEPS + lane]);
#pragma unroll
            for (int o = 1; o < 32; o <<= 1) {
                int t = __shfl_up_sync(0xffffffffu, v, o);
                if (lane >= o) v += t;
            }
            out[g2 * STEPS + lane] = (float)v;
            g_hist[g2 * STEPS + lane] = 0;
        }
        if (tid == 0) g_count = 0u;
    }
}

extern "C" void kernel_launch(void* const* d_in, const int* in_sizes, int n_in,
                              void* d_out, int out_size) {
    const float* x = (const float*)d_in[0];
    float* out = (float*)d_out;
    (void)in_sizes; (void)n_in; (void)out_size;
    ecc_kernel<<<GRID, TPB>>>(x, out);
}

// round 10
// speedup vs baseline: 1.3070x; 1.3070x over previous
#include <cuda_runtime.h>

#define W 224
#define H 224
#define BC 192
#define STEPS 32
#define BANDS 4
#define RPB 56              // bands 0-2: 56 full rows; band 3: 55 full + bottom
#define TPB 256
#define NW 8
#define GRID (BC * BANDS)   // 768

// g_hist[bc][j] accumulates the cumulative Euler characteristic at t_j.
__device__ int g_hist[BC * STEPS];
__device__ unsigned int g_count;

template <int IMM>
__device__ __forceinline__ unsigned lop3(unsigned a, unsigned b, unsigned c) {
    unsigned r;
    asm("lop3.b32 %0, %1, %2, %3, %4;" : "=r"(r) : "r"(a), "r"(b), "r"(c), "n"(IMM));
    return r;
}

// Alive mask: bit j set iff t_j >= f. Bit-exact (validated R6-R9):
// ceil anchor + two exact-grid fixups, branchless.
__device__ __forceinline__ unsigned maskof(float f) {
    const float step = 1.0f / 31.0f;
    float fr = ceilf(f * 31.0f);                       // integral, in [0, 31]
    int g = __float2int_rn(fr);
    g -= (__fmaf_rn(fr, step, -step) >= f) ? 1 : 0;    // t_{fr-1} >= f
    g += (fr < 31.0f && fr * step < f) ? 1 : 0;        // t_fr < f (t_31 = 1.0)
    return 0xFFFFFFFFu << g;
}

__device__ __forceinline__ void csa5(unsigned c[5], unsigned x) {
    unsigned t;
    t = c[0] & x; c[0] ^= x; x = t;
    t = c[1] & x; c[1] ^= x; x = t;
    t = c[2] & x; c[2] ^= x; x = t;
    t = c[3] & x; c[3] ^= x; x = t;
    c[4] ^= x;
}
// 3:2 compressor into weight-1 / weight-2 plane sets (explicit LOP3).
__device__ __forceinline__ void add3(unsigned A1[5], unsigned A2[5],
                                     unsigned x, unsigned y, unsigned z) {
    unsigned s = lop3<0x96>(x, y, z);   // a^b^c
    unsigned c = lop3<0xE8>(x, y, z);   // majority
    csa5(A1, s);
    csa5(A2, c);
}
__device__ __forceinline__ void add2(unsigned A1[5], unsigned A2[5],
                                     unsigned x, unsigned y) {
    csa5(A1, x ^ y);
    csa5(A2, x & y);
}

// Warp 32x32 bit transpose: out lane j bit k = in lane k bit j.
__device__ __forceinline__ unsigned tr32(unsigned v, int lane) {
    unsigned w;
    w = __shfl_xor_sync(0xffffffffu, v, 16);
    v = (lane & 16) ? ((v & 0xFFFF0000u) | ((w >> 16) & 0x0000FFFFu))
                    : ((v & 0x0000FFFFu) | ((w << 16) & 0xFFFF0000u));
    w = __shfl_xor_sync(0xffffffffu, v, 8);
    v = (lane & 8)  ? ((v & 0xFF00FF00u) | ((w >> 8)  & 0x00FF00FFu))
                    : ((v & 0x00FF00FFu) | ((w << 8)  & 0xFF00FF00u));
    w = __shfl_xor_sync(0xffffffffu, v, 4);
    v = (lane & 4)  ? ((v & 0xF0F0F0F0u) | ((w >> 4)  & 0x0F0F0F0Fu))
                    : ((v & 0x0F0F0F0Fu) | ((w << 4)  & 0xF0F0F0F0u));
    w = __shfl_xor_sync(0xffffffffu, v, 2);
    v = (lane & 2)  ? ((v & 0xCCCCCCCCu) | ((w >> 2)  & 0x33333333u))
                    : ((v & 0x33333333u) | ((w << 2)  & 0xCCCCCCCCu));
    w = __shfl_xor_sync(0xffffffffu, v, 1);
    v = (lane & 1)  ? ((v & 0xAAAAAAAAu) | ((w >> 1)  & 0x55555555u))
                    : ((v & 0x55555555u) | ((w << 1)  & 0xAAAAAAAAu));
    return v;
}

struct St { const float* p; unsigned m, mr; };

// One pixel row -> P (net +1 cells) and N (net -1 cells), one LOP3 per term:
//   mrEff = (mr & hasRM) | (mn & ~hasRM)      -> 0xE4(mr, mn, hasRM)
//   P     = m & ~mrEff & aM                   -> 0x20(m, mrEff, aM)
//   t2    = (mr & mnr) | ~hasRM               -> 0xD5(mr, mnr, hasRM)
//   N     = m & mn & ~t2                      -> 0x40(m, mn, t2)
__device__ __forceinline__ void rowPN(St& s, unsigned aM, unsigned hasRM,
                                      unsigned& P, unsigned& N, int ofs) {
    const unsigned mn  = maskof(__ldg(s.p + ofs));
    const unsigned mnr = __shfl_down_sync(0xffffffffu, mn, 1);
    const unsigned mrE = lop3<0xE4>(s.mr, mn, hasRM);
    P = lop3<0x20>(s.m, mrE, aM);
    const unsigned t2  = lop3<0xD5>(s.mr, mnr, hasRM);
    N = lop3<0x40>(s.m, mn, t2);
    s.m = mn; s.mr = mnr;
}

__global__ __launch_bounds__(TPB) void ecc_kernel(const float* __restrict__ x,
                                                  float* __restrict__ out) {
    __shared__ int s_cnt[NW][STEPS];
    __shared__ bool s_last;

    const int tid  = threadIdx.x;
    const int wid  = tid >> 5;
    const int lane = tid & 31;
    const int col  = wid * 31 + lane;           // overlapped-warp column map
    const int bc   = blockIdx.x >> 2;
    const int band = blockIdx.x & 3;
    const int r0   = band * RPB;

    const bool act       = (lane < 31) && (col <= 223);
    const unsigned aM    = act ? 0xFFFFFFFFu : 0u;
    const unsigned hasRM = (act && col < 223) ? 0xFFFFFFFFu : 0u;
    const int colc = (col <= 223) ? col : 223;

    unsigned P1[5] = {0,0,0,0,0}, P2[5] = {0,0,0,0,0};
    unsigned N1[5] = {0,0,0,0,0}, N2[5] = {0,0,0,0,0};

    St s;
    s.p  = x + (size_t)bc * (H * W) + (size_t)r0 * W + colc;
    s.m  = maskof(__ldg(s.p));
    s.mr = __shfl_down_sync(0xffffffffu, s.m, 1);

    // 18 triples = 54 rows for all bands.
#pragma unroll 6
    for (int it = 0; it < 18; it++) {
        unsigned Pa, Na, Pb, Nb, Pc, Nc;
        rowPN(s, aM, hasRM, Pa, Na, W);
        rowPN(s, aM, hasRM, Pb, Nb, 2 * W);
        rowPN(s, aM, hasRM, Pc, Nc, 3 * W);
        s.p += 3 * W;
        add3(P1, P2, Pa, Pb, Pc);
        add3(N1, N2, Na, Nb, Nc);
    }

    if (band != BANDS - 1) {
        // rows 54, 55 of the band (both full).
        unsigned Pa, Na, Pb, Nb;
        rowPN(s, aM, hasRM, Pa, Na, W);
        rowPN(s, aM, hasRM, Pb, Nb, 2 * W);
        add2(P1, P2, Pa, Pb);
        add2(N1, N2, Na, Nb);
    } else {
        // row 222 (full) + row 223 (vertex + h-edge only).
        unsigned Pa, Na;
        rowPN(s, aM, hasRM, Pa, Na, W);
        const unsigned Pb = lop3<0x20>(s.m, s.mr & hasRM, aM);  // m & ~mrEff & aM
        add2(P1, P2, Pa, Pb);
        csa5(N1, Na);
    }

    // Epilogue: transpose planes, weighted popcounts -> chi @ bin `lane`.
    int cnt = 0;
#pragma unroll
    for (int i = 0; i < 5; i++) cnt += (int)__popc(tr32(P1[i], lane)) << i;
#pragma unroll
    for (int i = 0; i < 5; i++) cnt += (int)__popc(tr32(P2[i], lane)) << (i + 1);
#pragma unroll
    for (int i = 0; i < 5; i++) cnt -= (int)__popc(tr32(N1[i], lane)) << i;
#pragma unroll
    for (int i = 0; i < 5; i++) cnt -= (int)__popc(tr32(N2[i], lane)) << (i + 1);

    s_cnt[wid][lane] = cnt;
    __syncthreads();
    if (wid == 0) {
        int sum = 0;
#pragma unroll
        for (int w2 = 0; w2 < NW; w2++) sum += s_cnt[w2][lane];
        atomicAdd(&g_hist[bc * STEPS + lane], sum);
    }

    // Last-block-done: write out + reset scratch for next graph replay.
    __threadfence();
    __syncthreads();
    if (tid == 0)
        s_last = (atomicAdd(&g_count, 1u) == (unsigned)(GRID - 1));
    __syncthreads();

    if (s_last) {
        __threadfence();
        for (int g2 = wid; g2 < BC; g2 += NW) {
            const int vv = __ldcg(&g_hist[g2 * STEPS + lane]);
            out[g2 * STEPS + lane] = (float)vv;
            g_hist[g2 * STEPS + lane] = 0;
        }
        if (tid == 0) g_count = 0u;
    }
}

extern "C" void kernel_launch(void* const* d_in, const int* in_sizes, int n_in,
                              void* d_out, int out_size) {
    const float* x = (const float*)d_in[0];
    float* out = (float*)d_out;
    (void)in_sizes; (void)n_in; (void)out_size;
    ecc_kernel<<<GRID, TPB>>>(x, out);
}

// round 11
// speedup vs baseline: 1.3943x; 1.0667x over previous
#include <cuda_runtime.h>

#define W 224
#define H 224
#define BC 192
#define STEPS 32
#define BANDS 3
#define RPB 75              // bands 0,1: 75 full rows; band 2: 73 full + bottom
#define TPB 256
#define NW 8
#define GRID (BC * BANDS)   // 576 <= 148 SMs * 4 blocks@62regs = single wave

// g_hist[bc][j] accumulates the cumulative Euler characteristic at t_j.
__device__ int g_hist[BC * STEPS];
__device__ unsigned int g_count;

template <int IMM>
__device__ __forceinline__ unsigned lop3(unsigned a, unsigned b, unsigned c) {
    unsigned r;
    asm("lop3.b32 %0, %1, %2, %3, %4;" : "=r"(r) : "r"(a), "r"(b), "r"(c), "n"(IMM));
    return r;
}

// Alive mask: bit j set iff t_j >= f. Bit-exact (validated R6-R10):
// ceil anchor + two exact-grid fixups, branchless.
__device__ __forceinline__ unsigned maskof(float f) {
    const float step = 1.0f / 31.0f;
    float fr = ceilf(f * 31.0f);                       // integral, in [0, 31]
    int g = __float2int_rn(fr);
    g -= (__fmaf_rn(fr, step, -step) >= f) ? 1 : 0;    // t_{fr-1} >= f
    g += (fr < 31.0f && fr * step < f) ? 1 : 0;        // t_fr < f (t_31 = 1.0)
    return 0xFFFFFFFFu << g;
}

__device__ __forceinline__ void csa5(unsigned c[5], unsigned x) {
    unsigned t;
    t = c[0] & x; c[0] ^= x; x = t;
    t = c[1] & x; c[1] ^= x; x = t;
    t = c[2] & x; c[2] ^= x; x = t;
    t = c[3] & x; c[3] ^= x; x = t;
    c[4] ^= x;
}
// 3:2 compressor into weight-1 / weight-2 plane sets (explicit LOP3).
__device__ __forceinline__ void add3(unsigned A1[5], unsigned A2[5],
                                     unsigned x, unsigned y, unsigned z) {
    unsigned s = lop3<0x96>(x, y, z);   // a^b^c
    unsigned c = lop3<0xE8>(x, y, z);   // majority
    csa5(A1, s);
    csa5(A2, c);
}
__device__ __forceinline__ void add2(unsigned A1[5], unsigned A2[5],
                                     unsigned x, unsigned y) {
    csa5(A1, x ^ y);
    csa5(A2, x & y);
}

// Warp 32x32 bit transpose: out lane j bit k = in lane k bit j.
__device__ __forceinline__ unsigned tr32(unsigned v, int lane) {
    unsigned w;
    w = __shfl_xor_sync(0xffffffffu, v, 16);
    v = (lane & 16) ? ((v & 0xFFFF0000u) | ((w >> 16) & 0x0000FFFFu))
                    : ((v & 0x0000FFFFu) | ((w << 16) & 0xFFFF0000u));
    w = __shfl_xor_sync(0xffffffffu, v, 8);
    v = (lane & 8)  ? ((v & 0xFF00FF00u) | ((w >> 8)  & 0x00FF00FFu))
                    : ((v & 0x00FF00FFu) | ((w << 8)  & 0xFF00FF00u));
    w = __shfl_xor_sync(0xffffffffu, v, 4);
    v = (lane & 4)  ? ((v & 0xF0F0F0F0u) | ((w >> 4)  & 0x0F0F0F0Fu))
                    : ((v & 0x0F0F0F0Fu) | ((w << 4)  & 0xF0F0F0F0u));
    w = __shfl_xor_sync(0xffffffffu, v, 2);
    v = (lane & 2)  ? ((v & 0xCCCCCCCCu) | ((w >> 2)  & 0x33333333u))
                    : ((v & 0x33333333u) | ((w << 2)  & 0xCCCCCCCCu));
    w = __shfl_xor_sync(0xffffffffu, v, 1);
    v = (lane & 1)  ? ((v & 0xAAAAAAAAu) | ((w >> 1)  & 0x55555555u))
                    : ((v & 0x55555555u) | ((w << 1)  & 0xAAAAAAAAu));
    return v;
}

struct St { const float* p; unsigned m, mr; };

// One pixel row -> P (net +1 cells) and N (net -1 cells), one LOP3 per term:
//   mrEff = (mr & hasRM) | (mn & ~hasRM)      -> 0xE4(mr, mn, hasRM)
//   P     = m & ~mrEff & aM                   -> 0x20(m, mrEff, aM)
//   t2    = (mr & mnr) | ~hasRM               -> 0xD5(mr, mnr, hasRM)
//   N     = m & mn & ~t2                      -> 0x40(m, mn, t2)
__device__ __forceinline__ void rowPN(St& s, unsigned aM, unsigned hasRM,
                                      unsigned& P, unsigned& N, int ofs) {
    const unsigned mn  = maskof(__ldg(s.p + ofs));
    const unsigned mnr = __shfl_down_sync(0xffffffffu, mn, 1);
    const unsigned mrE = lop3<0xE4>(s.mr, mn, hasRM);
    P = lop3<0x20>(s.m, mrE, aM);
    const unsigned t2  = lop3<0xD5>(s.mr, mnr, hasRM);
    N = lop3<0x40>(s.m, mn, t2);
    s.m = mn; s.mr = mnr;
}

__global__ __launch_bounds__(TPB) void ecc_kernel(const float* __restrict__ x,
                                                  float* __restrict__ out) {
    __shared__ int s_cnt[NW][STEPS];
    __shared__ bool s_last;

    const int tid  = threadIdx.x;
    const int wid  = tid >> 5;
    const int lane = tid & 31;
    const int col  = wid * 31 + lane;           // overlapped-warp column map
    const int bc   = blockIdx.x / BANDS;
    const int band = blockIdx.x % BANDS;
    const int r0   = band * RPB;

    const bool act       = (lane < 31) && (col <= 223);
    const unsigned aM    = act ? 0xFFFFFFFFu : 0u;
    const unsigned hasRM = (act && col < 223) ? 0xFFFFFFFFu : 0u;
    const int colc = (col <= 223) ? col : 223;

    unsigned P1[5] = {0,0,0,0,0}, P2[5] = {0,0,0,0,0};
    unsigned N1[5] = {0,0,0,0,0}, N2[5] = {0,0,0,0,0};

    St s;
    s.p  = x + (size_t)bc * (H * W) + (size_t)r0 * W + colc;
    s.m  = maskof(__ldg(s.p));
    s.mr = __shfl_down_sync(0xffffffffu, s.m, 1);

    // bands 0,1: 25 triples (75 full rows); band 2: 24 triples (72 rows).
    const int ntrip = (band == BANDS - 1) ? 24 : 25;
#pragma unroll 5
    for (int it = 0; it < ntrip; it++) {
        unsigned Pa, Na, Pb, Nb, Pc, Nc;
        rowPN(s, aM, hasRM, Pa, Na, W);
        rowPN(s, aM, hasRM, Pb, Nb, 2 * W);
        rowPN(s, aM, hasRM, Pc, Nc, 3 * W);
        s.p += 3 * W;
        add3(P1, P2, Pa, Pb, Pc);
        add3(N1, N2, Na, Nb, Nc);
    }

    if (band == BANDS - 1) {
        // row 222 (full) + row 223 (vertex + h-edge only).
        unsigned Pa, Na;
        rowPN(s, aM, hasRM, Pa, Na, W);
        const unsigned Pb = lop3<0x20>(s.m, s.mr & hasRM, aM);  // m & ~mrEff & aM
        add2(P1, P2, Pa, Pb);
        csa5(N1, Na);
    }

    // Epilogue: transpose planes, weighted popcounts -> chi @ bin `lane`.
    int cnt = 0;
#pragma unroll
    for (int i = 0; i < 5; i++) cnt += (int)__popc(tr32(P1[i], lane)) << i;
#pragma unroll
    for (int i = 0; i < 5; i++) cnt += (int)__popc(tr32(P2[i], lane)) << (i + 1);
#pragma unroll
    for (int i = 0; i < 5; i++) cnt -= (int)__popc(tr32(N1[i], lane)) << i;
#pragma unroll
    for (int i = 0; i < 5; i++) cnt -= (int)__popc(tr32(N2[i], lane)) << (i + 1);

    s_cnt[wid][lane] = cnt;
    __syncthreads();
    if (wid == 0) {
        int sum = 0;
#pragma unroll
        for (int w2 = 0; w2 < NW; w2++) sum += s_cnt[w2][lane];
        atomicAdd(&g_hist[bc * STEPS + lane], sum);
    }

    // Last-block-done: write out + reset scratch for next graph replay.
    __threadfence();
    __syncthreads();
    if (tid == 0)
        s_last = (atomicAdd(&g_count, 1u) == (unsigned)(GRID - 1));
    __syncthreads();

    if (s_last) {
        __threadfence();
        for (int g2 = wid; g2 < BC; g2 += NW) {
            const int vv = __ldcg(&g_hist[g2 * STEPS + lane]);
            out[g2 * STEPS + lane] = (float)vv;
            g_hist[g2 * STEPS + lane] = 0;
        }
        if (tid == 0) g_count = 0u;
    }
}

extern "C" void kernel_launch(void* const* d_in, const int* in_sizes, int n_in,
                              void* d_out, int out_size) {
    const float* x = (const float*)d_in[0];
    float* out = (float*)d_out;
    (void)in_sizes; (void)n_in; (void)out_size;
    ecc_kernel<<<GRID, TPB>>>(x, out);
}

// round 12
// speedup vs baseline: 1.4907x; 1.0692x over previous
#include <cuda_runtime.h>

#define W 224
#define H 224
#define BC 192
#define STEPS 32
#define BANDS 3
#define RPB 75              // bands 0,1: 75 full rows; band 2: 73 full + bottom
#define TPB 256
#define NW 8
#define GRID (BC * BANDS)   // 576 <= 148 * 4 blocks -> single wave

// g_hist[bc][j] accumulates the cumulative Euler characteristic at t_j.
__device__ int g_hist[BC * STEPS];
__device__ unsigned int g_count;

template <int IMM>
__device__ __forceinline__ unsigned lop3(unsigned a, unsigned b, unsigned c) {
    unsigned r;
    asm("lop3.b32 %0, %1, %2, %3, %4;" : "=r"(r) : "r"(a), "r"(b), "r"(c), "n"(IMM));
    return r;
}

// Alive mask: bit j set iff t_j >= f. Bit-exact (validated R6-R11).
__device__ __forceinline__ unsigned maskof(float f) {
    const float step = 1.0f / 31.0f;
    float fr = ceilf(f * 31.0f);                       // integral, in [0, 31]
    int g = __float2int_rn(fr);
    g -= (__fmaf_rn(fr, step, -step) >= f) ? 1 : 0;    // t_{fr-1} >= f
    g += (fr < 31.0f && fr * step < f) ? 1 : 0;        // t_fr < f (t_31 = 1.0)
    return 0xFFFFFFFFu << g;
}

__device__ __forceinline__ void csa5(unsigned c[5], unsigned x) {
    unsigned t;
    t = c[0] & x; c[0] ^= x; x = t;
    t = c[1] & x; c[1] ^= x; x = t;
    t = c[2] & x; c[2] ^= x; x = t;
    t = c[3] & x; c[3] ^= x; x = t;
    c[4] ^= x;
}

// Warp 32x32 bit transpose: out lane j bit k = in lane k bit j.
__device__ __forceinline__ unsigned tr32(unsigned v, int lane) {
    unsigned w;
    w = __shfl_xor_sync(0xffffffffu, v, 16);
    v = (lane & 16) ? ((v & 0xFFFF0000u) | ((w >> 16) & 0x0000FFFFu))
                    : ((v & 0x0000FFFFu) | ((w << 16) & 0xFFFF0000u));
    w = __shfl_xor_sync(0xffffffffu, v, 8);
    v = (lane & 8)  ? ((v & 0xFF00FF00u) | ((w >> 8)  & 0x00FF00FFu))
                    : ((v & 0x00FF00FFu) | ((w << 8)  & 0xFF00FF00u));
    w = __shfl_xor_sync(0xffffffffu, v, 4);
    v = (lane & 4)  ? ((v & 0xF0F0F0F0u) | ((w >> 4)  & 0x0F0F0F0Fu))
                    : ((v & 0x0F0F0F0Fu) | ((w << 4)  & 0xF0F0F0F0u));
    w = __shfl_xor_sync(0xffffffffu, v, 2);
    v = (lane & 2)  ? ((v & 0xCCCCCCCCu) | ((w >> 2)  & 0x33333333u))
                    : ((v & 0x33333333u) | ((w << 2)  & 0xCCCCCCCCu));
    w = __shfl_xor_sync(0xffffffffu, v, 1);
    v = (lane & 1)  ? ((v & 0xAAAAAAAAu) | ((w >> 1)  & 0x55555555u))
                    : ((v & 0x55555555u) | ((w << 1)  & 0xAAAAAAAAu));
    return v;
}

// One pixel row from prefetched f: emits P (net +1) and NN = ~N (net -1,
// complemented so a 6:3 compressor can fold P and N together).
//   mrE = (mr & hasRM) | (mn & ~hasRM)   -> 0xE4(mr, mn, hasRM)
//   P   = m & ~mrE & aM                  -> 0x20(m, mrE, aM)
//   t2  = (mr & mnr) | ~hasRM            -> 0xD5(mr, mnr, hasRM)
//   NN  = ~(m & mn & ~t2)                -> 0xBF(m, mn, t2)
__device__ __forceinline__ void rowPN(unsigned& m, unsigned& mr, float f,
                                      unsigned aM, unsigned hasRM,
                                      unsigned& P, unsigned& NN) {
    const unsigned mn  = maskof(f);
    const unsigned mnr = __shfl_down_sync(0xffffffffu, mn, 1);
    const unsigned mrE = lop3<0xE4>(mr, mn, hasRM);
    P  = lop3<0x20>(m, mrE, aM);
    const unsigned t2  = lop3<0xD5>(mr, mnr, hasRM);
    NN = lop3<0xBF>(m, mn, t2);
    m = mn; mr = mnr;
}

// 6:3 compress {Pa,Pb,Pc,Na,Nb,Nc} (N's complemented) into w1/w2/w4 planes.
__device__ __forceinline__ void add6(unsigned A1[5], unsigned A2[5], unsigned A4[5],
                                     unsigned Pa, unsigned Pb, unsigned Pc,
                                     unsigned Na, unsigned Nb, unsigned Nc) {
    unsigned sP = lop3<0x96>(Pa, Pb, Pc), cP = lop3<0xE8>(Pa, Pb, Pc);
    unsigned sN = lop3<0x96>(Na, Nb, Nc), cN = lop3<0xE8>(Na, Nb, Nc);
    unsigned s  = sP ^ sN, c3 = sP & sN;
    unsigned c  = lop3<0x96>(cP, cN, c3), d = lop3<0xE8>(cP, cN, c3);
    csa5(A1, s); csa5(A2, c); csa5(A4, d);
}

__global__ __launch_bounds__(TPB) void ecc_kernel(const float* __restrict__ x,
                                                  float* __restrict__ out) {
    __shared__ int s_cnt[NW][STEPS];
    __shared__ bool s_last;

    const int tid  = threadIdx.x;
    const int wid  = tid >> 5;
    const int lane = tid & 31;
    const int col  = wid * 31 + lane;           // overlapped-warp column map
    const int bc   = blockIdx.x / BANDS;
    const int band = blockIdx.x % BANDS;
    const int r0   = band * RPB;

    const bool act       = (lane < 31) && (col <= 223);
    const unsigned aM    = act ? 0xFFFFFFFFu : 0u;
    const unsigned hasRM = (act && col < 223) ? 0xFFFFFFFFu : 0u;
    const int colc = (col <= 223) ? col : 223;

    unsigned A1[5] = {0,0,0,0,0}, A2[5] = {0,0,0,0,0}, A4[5] = {0,0,0,0,0};

    const float* p = x + (size_t)bc * (H * W) + (size_t)r0 * W + colc;
    unsigned m  = maskof(__ldg(p));
    unsigned mr = __shfl_down_sync(0xffffffffu, m, 1);

    const int ntrip = (band == BANDS - 1) ? 24 : 25;

    // Software pipeline: prefetch the next triple's floats before processing.
    float fa = __ldg(p + W), fb = __ldg(p + 2 * W), fc = __ldg(p + 3 * W);
    p += 3 * W;
#pragma unroll 2
    for (int it = 0; it < ntrip - 1; it++) {
        const float ga = __ldg(p + W), gb = __ldg(p + 2 * W), gc = __ldg(p + 3 * W);
        p += 3 * W;
        unsigned Pa, Na, Pb, Nb, Pc, Nc;
        rowPN(m, mr, fa, aM, hasRM, Pa, Na);
        rowPN(m, mr, fb, aM, hasRM, Pb, Nb);
        rowPN(m, mr, fc, aM, hasRM, Pc, Nc);
        add6(A1, A2, A4, Pa, Pb, Pc, Na, Nb, Nc);
        fa = ga; fb = gb; fc = gc;
    }
    {
        unsigned Pa, Na, Pb, Nb, Pc, Nc;
        rowPN(m, mr, fa, aM, hasRM, Pa, Na);
        rowPN(m, mr, fb, aM, hasRM, Pb, Nb);
        rowPN(m, mr, fc, aM, hasRM, Pc, Nc);
        add6(A1, A2, A4, Pa, Pb, Pc, Na, Nb, Nc);
    }

    int nN = 3 * ntrip;                        // complemented-N rows folded in
    if (band == BANDS - 1) {
        // row 222 (full) + row 223 (vertex + h-edge only).
        unsigned Pa, Na;
        rowPN(m, mr, __ldg(p + W), aM, hasRM, Pa, Na);
        const unsigned Pb = lop3<0x20>(m, mr & hasRM, aM);   // bottom row
        const unsigned s = lop3<0x96>(Pa, Na, Pb), c = lop3<0xE8>(Pa, Na, Pb);
        csa5(A1, s); csa5(A2, c);
        nN += 1;
    }

    // Epilogue: transpose 15 planes, weighted popcounts, subtract the
    // complement offset (each ~N row contributed +1 to every bin, x32 lanes).
    int cnt = -(nN << 5);
#pragma unroll
    for (int i = 0; i < 5; i++) cnt += (int)__popc(tr32(A1[i], lane)) << i;
#pragma unroll
    for (int i = 0; i < 5; i++) cnt += (int)__popc(tr32(A2[i], lane)) << (i + 1);
#pragma unroll
    for (int i = 0; i < 5; i++) cnt += (int)__popc(tr32(A4[i], lane)) << (i + 2);

    s_cnt[wid][lane] = cnt;
    __syncthreads();
    if (wid == 0) {
        int sum = 0;
#pragma unroll
        for (int w2 = 0; w2 < NW; w2++) sum += s_cnt[w2][lane];
        atomicAdd(&g_hist[bc * STEPS + lane], sum);
    }

    // Last-block-done: write out + reset scratch for next graph replay.
    __threadfence();
    __syncthreads();
    if (tid == 0)
        s_last = (atomicAdd(&g_count, 1u) == (unsigned)(GRID - 1));
    __syncthreads();

    if (s_last) {
        __threadfence();
        for (int g2 = wid; g2 < BC; g2 += NW) {
            const int vv = __ldcg(&g_hist[g2 * STEPS + lane]);
            out[g2 * STEPS + lane] = (float)vv;
            g_hist[g2 * STEPS + lane] = 0;
        }
        if (tid == 0) g_count = 0u;
    }
}

extern "C" void kernel_launch(void* const* d_in, const int* in_sizes, int n_in,
                              void* d_out, int out_size) {
    const float* x = (const float*)d_in[0];
    float* out = (float*)d_out;
    (void)in_sizes; (void)n_in; (void)out_size;
    ecc_kernel<<<GRID, TPB>>>(x, out);
}